// round 15
// baseline (speedup 1.0000x reference)
#include <cuda_runtime.h>
#include <cuda_fp16.h>
#include <math_constants.h>
#include <cstdint>

#define Bb   4
#define NQ   4096
#define NP   2048
#define D    256
#define KNN  16
#define PAIR_ROWS (Bb*NQ*KNN)   /* 262144 */

// ================= PTX helpers (baseline ISA — no tcgen05) =================
__device__ __forceinline__ uint32_t smem_to_u32(const void* p) {
    uint32_t a;
    asm("{ .reg .u64 t; cvta.to.shared.u64 t, %1; cvt.u32.u64 %0, t; }" : "=r"(a) : "l"(p));
    return a;
}
#define CP_ASYNC16(dst, src) \
    asm volatile("cp.async.cg.shared.global [%0], [%1], 16;" :: "r"(dst), "l"(src))
#define CP_COMMIT() asm volatile("cp.async.commit_group;" ::: "memory")
template<int N> __device__ __forceinline__ void cp_wait() {
    asm volatile("cp.async.wait_group %0;" :: "n"(N) : "memory");
}
#define LDSM_X4(r0,r1,r2,r3, addr) \
    asm volatile("ldmatrix.sync.aligned.m8n8.x4.shared.b16 {%0,%1,%2,%3}, [%4];" \
        : "=r"(r0), "=r"(r1), "=r"(r2), "=r"(r3) : "r"(addr))
#define MMA16816(cc, a0,a1,a2,a3, b0,b1) \
    asm volatile("mma.sync.aligned.m16n8k16.row.col.f32.f16.f16.f32 " \
        "{%0,%1,%2,%3}, {%4,%5,%6,%7}, {%8,%9}, {%0,%1,%2,%3};" \
        : "+f"((cc)[0]), "+f"((cc)[1]), "+f"((cc)[2]), "+f"((cc)[3]) \
        : "r"(a0), "r"(a1), "r"(a2), "r"(a3), "r"(b0), "r"(b1))
#define SW128(off) ((off) ^ (((off) >> 3) & 0x70))

// ================= scratch (device globals) =================
__device__ __align__(16) __half g_ckq16[Bb*NP*D]; // cq + c0 - (Wg1@Wk)points  (fp16, L2)
__device__ __align__(16) __half g_v16 [Bb*NP*D];  // points @ Wv^T (fp16, L2)
__device__ __align__(16) __half g_b316[Bb*NP*D];  // Wd1 @ xyz            (fp16)
__device__ __align__(16) __half g_aq16[Bb*NQ*D];  // Wd1 @ xyz_q + bd1    (fp16)
__device__ int    g_knn[Bb*NQ*KNN];
__device__ __align__(16) __half g_Wcat16[2*D*D];  // [Wd2 ; Md=Wg1@Wd2] fp16
__device__ __align__(16) __half g_Wg2_16[D*D];
__device__ float  g_Wkk [D*D];          // Wg1@Wk (fp32, for sgemm)
__device__ float  g_cq[Bb*D];           // Wg1 @ (Wq lat)
__device__ float  g_c0[D];              // Wg1@bd2 + bg1
__device__ float  g_ag[Bb*D];           // gamma-MLP output for global token
__device__ float  g_vg[Bb*D];           // Wvg lat

// ================= k_prep =================
__device__ __forceinline__ float dot256(const float* __restrict__ w, const float* __restrict__ s)
{
    float acc = 0.f;
    #pragma unroll 8
    for (int c = 0; c < 256; c++) acc = fmaf(w[c], s[c], acc);
    return acc;
}

__global__ void k_prep(const float* __restrict__ Wd2, const float* __restrict__ Wg1,
                       const float* __restrict__ Wk,  const float* __restrict__ Wg2,
                       const float* __restrict__ lat,
                       const float* __restrict__ Wq,  const float* __restrict__ Wkg,
                       const float* __restrict__ Wvg, const float* __restrict__ bg1,
                       const float* __restrict__ bg2, const float* __restrict__ bd2)
{
    int blk = blockIdx.x;
    int tid = threadIdx.x;
    if (blk < 1024) {
        int gid = blk * 256 + tid;
        if (gid < D*D) {
            g_Wcat16[gid] = __float2half(Wd2[gid]);
        } else if (gid < 2*D*D) {
            int i = gid - D*D; int f = i >> 8, j = i & 255;
            float acc = 0.f;
            #pragma unroll 8
            for (int c = 0; c < D; c++) acc = fmaf(Wg1[f*D+c], Wd2[c*D+j], acc);
            g_Wcat16[D*D + i] = __float2half(acc);
        } else if (gid < 3*D*D) {
            int i = gid - 2*D*D; int f = i >> 8, j = i & 255;
            float acc = 0.f;
            #pragma unroll 8
            for (int c = 0; c < D; c++) acc = fmaf(Wg1[f*D+c], Wk[c*D+j], acc);
            g_Wkk[i] = acc;
        } else {
            int i = gid - 3*D*D;
            g_Wg2_16[i] = __float2half(Wg2[i]);
        }
        return;
    }
    __shared__ float s_in[256], s_qa[256], s_x[256], s_t[256];
    int f = tid;
    {
        float acc = bg1[f];
        #pragma unroll 8
        for (int c = 0; c < 256; c++) acc = fmaf(Wg1[f*256+c], bd2[c], acc);
        g_c0[f] = acc;
    }
    for (int b = 0; b < Bb; b++) {
        __syncthreads();
        s_in[f] = lat[b*256+f];
        __syncthreads();
        float qa = dot256(Wq  + f*256, s_in);
        float kg = dot256(Wkg + f*256, s_in);
        g_vg[b*256+f] = dot256(Wvg + f*256, s_in);
        __syncthreads();
        s_qa[f] = qa;
        s_x [f] = qa - kg;
        __syncthreads();
        g_cq[b*256+f] = dot256(Wg1 + f*256, s_qa);
        float tg = dot256(Wg1 + f*256, s_x) + bg1[f];
        s_t[f] = fmaxf(tg, 0.f);
        __syncthreads();
        g_ag[b*256+f] = dot256(Wg2 + f*256, s_t) + bg2[f];
    }
}

// ================= 3->256 coordinate projections (fp16 out) =================
__global__ void k_b3aq(const float* __restrict__ xyz, const float* __restrict__ xyz_q,
                       const float* __restrict__ Wd1, const float* __restrict__ bd1)
{
    int gid = blockIdx.x * 256 + threadIdx.x;
    int row = gid >> 8, f = gid & 255;
    float w0 = Wd1[f*3+0], w1 = Wd1[f*3+1], w2 = Wd1[f*3+2];
    if (row < Bb*NP) {
        const float* p = xyz + row*3;
        g_b316[gid] = __float2half(fmaf(w0, p[0], fmaf(w1, p[1], w2 * p[2])));
    } else {
        int r = row - Bb*NP; if (r >= Bb*NQ) return;
        const float* p = xyz_q + r*3;
        g_aq16[r*256+f] = __float2half(fmaf(w0, p[0], fmaf(w1, p[1], fmaf(w2, p[2], bd1[f]))));
    }
}

// ================= KNN: 32 queries/block, 8 subs/query, deterministic register merge
// dyn smem: [sp4: 2048 float4 = 32KB]
__global__ __launch_bounds__(256) void k_knn(const float* __restrict__ xyz,
                                             const float* __restrict__ xyz_q)
{
    extern __shared__ __align__(16) float4 sp4[];   // 2048 packed (x,y,z,n2)

    int tid = threadIdx.x;
    int qi = tid >> 3, sub = tid & 7;               // 32 queries x 8 subs
    int q  = blockIdx.x * 32 + qi;                  // b*4096 + q
    int b  = q >> 12;
    const float* xb = xyz + b * NP * 3;
    for (int i = tid; i < NP; i += 256) {
        float x = xb[i*3], y = xb[i*3+1], z = xb[i*3+2];
        sp4[i] = make_float4(x, y, z, x*x + y*y + z*z);
    }
    __syncthreads();
    const float* qp = xyz_q + q*3;
    float qx = qp[0], qy = qp[1], qz = qp[2];
    float qn2 = qx*qx + qy*qy + qz*qz;

    float dist[KNN]; int idxr[KNN];
    #pragma unroll
    for (int j = 0; j < KNN; j++) { dist[j] = CUDART_INF_F; idxr[j] = -1; }
    float worst = CUDART_INF_F; int ws = 0;
    #pragma unroll 2
    for (int k = 0; k < 256; k++) {
        int n = (k << 3) | sub;                      // warp-broadcast LDS.128
        float4 p = sp4[n];
        float dp = fmaf(qx, p.x, fmaf(qy, p.y, qz * p.z));
        float d2 = qn2 + p.w - 2.f * dp;             // identical formula to reference
        if (d2 < worst) {
            #pragma unroll
            for (int j = 0; j < KNN; j++) if (j == ws) { dist[j] = d2; idxr[j] = n; }
            worst = dist[0]; ws = 0;
            #pragma unroll
            for (int j = 1; j < KNN; j++) if (dist[j] > worst) { worst = dist[j]; ws = j; }
        }
    }

    // ---- deterministic merge: lexicographic (dist, idx) — tie-safe, all lanes agree
    #pragma unroll
    for (int s = 0; s < KNN; s++) {
        float best = CUDART_INF_F; int bn = 0x7FFFFFFF;
        #pragma unroll
        for (int j = 0; j < KNN; j++)
            if (dist[j] < best || (dist[j] == best && idxr[j] < bn)) {
                best = dist[j]; bn = idxr[j];
            }
        #pragma unroll
        for (int msk = 1; msk < 8; msk <<= 1) {
            float ov = __shfl_xor_sync(0xFFFFFFFFu, best, msk);
            int   on = __shfl_xor_sync(0xFFFFFFFFu, bn, msk);
            if (ov < best || (ov == best && on < bn)) { best = ov; bn = on; }
        }
        if (sub == 0) g_knn[q*KNN + s] = bn;
        #pragma unroll
        for (int j = 0; j < KNN; j++)
            if (idxr[j] == bn) dist[j] = CUDART_INF_F;   // idx unique -> exactly one slot
    }
}

// ================= SIMT fp32 GEMM for per-point ckq / v =================
__global__ __launch_bounds__(256) void sgemm(const float* __restrict__ A,
                                             const float* __restrict__ Wig,
                                             int mode)
{
    __shared__ float As[16][132];
    __shared__ float Ws[16][132];
    const float* W = (mode == 0) ? g_Wkk : Wig;
    const int bm = blockIdx.y << 7;
    const int bn = blockIdx.x << 7;
    const int tid = threadIdx.x;
    const int tx = tid & 15, ty = tid >> 4;

    float acc[8][8];
    #pragma unroll
    for (int i = 0; i < 8; i++)
        #pragma unroll
        for (int j = 0; j < 8; j++) acc[i][j] = 0.f;

    for (int k0 = 0; k0 < 256; k0 += 16) {
        #pragma unroll
        for (int i = 0; i < 2; i++) {
            int l = tid + (i << 8);
            int r = l >> 2, kc = (l & 3) << 2;
            float4 va = *(const float4*)(A + (bm + r) * 256 + k0 + kc);
            As[kc+0][r] = va.x; As[kc+1][r] = va.y; As[kc+2][r] = va.z; As[kc+3][r] = va.w;
            float4 vw = *(const float4*)(W + (bn + r) * 256 + k0 + kc);
            Ws[kc+0][r] = vw.x; Ws[kc+1][r] = vw.y; Ws[kc+2][r] = vw.z; Ws[kc+3][r] = vw.w;
        }
        __syncthreads();
        #pragma unroll
        for (int kk = 0; kk < 16; kk++) {
            float a[8], bb[8];
            *(float4*)(a)      = *(const float4*)&As[kk][ty << 3];
            *(float4*)(a + 4)  = *(const float4*)&As[kk][(ty << 3) + 4];
            *(float4*)(bb)     = *(const float4*)&Ws[kk][tx << 3];
            *(float4*)(bb + 4) = *(const float4*)&Ws[kk][(tx << 3) + 4];
            #pragma unroll
            for (int i = 0; i < 8; i++)
                #pragma unroll
                for (int j = 0; j < 8; j++) acc[i][j] = fmaf(a[i], bb[j], acc[i][j]);
        }
        __syncthreads();
    }
    int cc = bn + (tx << 3);
    if (mode == 0) {
        #pragma unroll
        for (int i = 0; i < 8; i++) {
            int m = bm + (ty << 3) + i;
            int b = m >> 11;
            __half hh[8];
            #pragma unroll
            for (int j = 0; j < 8; j++)
                hh[j] = __float2half(g_cq[b*256 + cc + j] + g_c0[cc + j] - acc[i][j]);
            *(uint4*)(g_ckq16 + (size_t)m*256 + cc) = *(uint4*)hh;
        }
    } else {
        #pragma unroll
        for (int i = 0; i < 8; i++) {
            int m = bm + (ty << 3) + i;
            __half hh[8];
            #pragma unroll
            for (int j = 0; j < 8; j++) hh[j] = __float2half(acc[i][j]);
            *(uint4*)(g_v16 + (size_t)m*256 + cc) = *(uint4*)hh;
        }
    }
}

// ===================================================================
// Fused pair pipeline. CTA = 128 pair rows (8 queries), 256 threads.
// SMEM: [A/h 64K][P/pos 64K][T/t 64K][B 2x16K] = 224KB, 1 CTA/SM.
// ===================================================================
struct WarpCtx {
    int lane, wid, warp_m, warp_n;
    int a_row, a_seg, b_row_base, b_seg;
};
__device__ __forceinline__ WarpCtx make_ctx(int tid) {
    WarpCtx w;
    w.lane = tid & 31; w.wid = tid >> 5;
    w.warp_m = w.wid >> 1; w.warp_n = w.wid & 1;
    int lr = w.lane & 7, sel = w.lane >> 3;
    w.a_row = w.warp_m*32 + lr + (sel & 1)*8;
    w.a_seg = sel >> 1;
    w.b_row_base = w.warp_n*64 + lr + (sel >> 1)*8;
    w.b_seg = sel & 1;
    return w;
}

__device__ __forceinline__ void mma_chunk(const WarpCtx& w, uint32_t bufA, uint32_t bufB,
                                          float acc[2][8][4])
{
    #pragma unroll
    for (int ks = 0; ks < 4; ks++) {
        uint32_t a[2][4], bf[4][4];
        #pragma unroll
        for (int mi = 0; mi < 2; mi++) {
            uint32_t ad = bufA + SW128(((w.a_row + mi*16) << 7) + ((w.a_seg + ks*2) << 4));
            LDSM_X4(a[mi][0], a[mi][1], a[mi][2], a[mi][3], ad);
        }
        #pragma unroll
        for (int nj = 0; nj < 4; nj++) {
            uint32_t bd = bufB + SW128(((w.b_row_base + nj*16) << 7) + ((w.b_seg + ks*2) << 4));
            LDSM_X4(bf[nj][0], bf[nj][1], bf[nj][2], bf[nj][3], bd);
        }
        #pragma unroll
        for (int mi = 0; mi < 2; mi++)
            #pragma unroll
            for (int ni = 0; ni < 8; ni++)
                MMA16816(acc[mi][ni], a[mi][0], a[mi][1], a[mi][2], a[mi][3],
                         bf[ni>>1][(ni&1)*2], bf[ni>>1][(ni&1)*2 + 1]);
    }
}

// One 128x128 half-GEMM: A (K=256, swizzled, 4x16KB at Abase), B streamed from Bop.
__device__ __forceinline__ void half_gemm(const WarpCtx& w, int tid,
                                          uint32_t Abase, uint32_t sB,
                                          const __half* __restrict__ Bop,
                                          float acc[2][8][4])
{
    const int lseg = tid & 7;
    #pragma unroll
    for (int mi = 0; mi < 2; mi++)
        #pragma unroll
        for (int ni = 0; ni < 8; ni++)
            #pragma unroll
            for (int k = 0; k < 4; k++) acc[mi][ni][k] = 0.f;
    #pragma unroll
    for (int c = 0; c < 2; c++) {
        #pragma unroll
        for (int i = 0; i < 4; i++) {
            int r = (tid >> 3) + (i << 5);
            CP_ASYNC16(sB + c*16384 + SW128((r << 7) + (lseg << 4)),
                       Bop + (size_t)r*256 + (c << 6) + (lseg << 3));
        }
        CP_COMMIT();
    }
    #pragma unroll
    for (int kc = 0; kc < 4; kc++) {
        if (kc < 3) cp_wait<1>(); else cp_wait<0>();
        __syncthreads();
        mma_chunk(w, Abase + kc*16384, sB + (kc & 1)*16384, acc);
        __syncthreads();
        if (kc < 2) {
            int c = kc + 2;
            #pragma unroll
            for (int i = 0; i < 4; i++) {
                int r = (tid >> 3) + (i << 5);
                CP_ASYNC16(sB + (c & 1)*16384 + SW128((r << 7) + (lseg << 4)),
                           Bop + (size_t)r*256 + (c << 6) + (lseg << 3));
            }
            CP_COMMIT();
        }
    }
}

__global__ __launch_bounds__(256, 1) void hg_fused(const float* __restrict__ bd2,
                                                   const float* __restrict__ bg2,
                                                   float* __restrict__ out)
{
    extern __shared__ __align__(16) char dynsm[];
    __shared__ float sBias[256];

    const int tid = threadIdx.x;
    const int bm  = blockIdx.x << 7;
    const int b   = bm >> 16;
    const uint32_t su = smem_to_u32(dynsm);
    const uint32_t sT = su + 131072;
    const uint32_t sB = su + 196608;
    WarpCtx w = make_ctx(tid);

    sBias[tid] = bd2[tid];

    // ---- regen h = relu(aq - b3[knn]) into A region (swizzled, 4x16KB chunks) ----
    const __half2 z2 = __floats2half2_rn(0.f, 0.f);
    #pragma unroll
    for (int c = 0; c < 4; c++) {
        #pragma unroll
        for (int i = 0; i < 4; i++) {
            int idx = tid + (i << 8);
            int r = idx >> 3, sg = idx & 7;
            int m = bm + r;
            int n = g_knn[m];
            uint4 ua = ((const uint4*)(g_aq16 + (size_t)(m >> 4)*256))[(c << 3) + sg];
            uint4 ub = ((const uint4*)(g_b316 + (size_t)(b*NP + n)*256))[(c << 3) + sg];
            __half2 a0 = *reinterpret_cast<__half2*>(&ua.x), p0 = *reinterpret_cast<__half2*>(&ub.x);
            __half2 a1 = *reinterpret_cast<__half2*>(&ua.y), p1 = *reinterpret_cast<__half2*>(&ub.y);
            __half2 a2 = *reinterpret_cast<__half2*>(&ua.z), p2 = *reinterpret_cast<__half2*>(&ub.z);
            __half2 a3 = *reinterpret_cast<__half2*>(&ua.w), p3 = *reinterpret_cast<__half2*>(&ub.w);
            __half2 h0 = __hmax2(__hsub2(a0, p0), z2);
            __half2 h1 = __hmax2(__hsub2(a1, p1), z2);
            __half2 h2 = __hmax2(__hsub2(a2, p2), z2);
            __half2 h3 = __hmax2(__hsub2(a3, p3), z2);
            uint4 u;
            u.x = reinterpret_cast<uint32_t&>(h0);
            u.y = reinterpret_cast<uint32_t&>(h1);
            u.z = reinterpret_cast<uint32_t&>(h2);
            u.w = reinterpret_cast<uint32_t&>(h3);
            *(uint4*)(dynsm + c*16384 + SW128((r << 7) + (sg << 4))) = u;
        }
    }

    float acc[2][8][4];

    // ---- GEMM pos (2 halves): P[:, nh*128+cl] = acc + bd2 ----
    #pragma unroll
    for (int nh = 0; nh < 2; nh++) {
        half_gemm(w, tid, su, sB, g_Wcat16 + (size_t)(nh << 7) * 256, acc);
        #pragma unroll
        for (int mi = 0; mi < 2; mi++)
            #pragma unroll
            for (int ni = 0; ni < 8; ni++) {
                int rl = w.warp_m*32 + mi*16 + (w.lane >> 2);
                int cl = w.warp_n*64 + ni*8 + ((w.lane & 3) << 1);
                int gcol = (nh << 7) + cl;
                int chunk = gcol >> 6, cin = gcol & 63;
                float bx = sBias[gcol], by = sBias[gcol+1];
                *(__half2*)(dynsm + 65536 + chunk*16384 + SW128((rl << 7) + (cin << 1))) =
                    __floats2half2_rn(acc[mi][ni][0] + bx, acc[mi][ni][1] + by);
                *(__half2*)(dynsm + 65536 + chunk*16384 + SW128(((rl+8) << 7) + (cin << 1))) =
                    __floats2half2_rn(acc[mi][ni][2] + bx, acc[mi][ni][3] + by);
            }
    }

    // ---- GEMM t (2 halves): T = relu(acc + ckq[knn]) ----
    #pragma unroll
    for (int nh = 0; nh < 2; nh++) {
        half_gemm(w, tid, su, sB, g_Wcat16 + (size_t)(256 + (nh << 7)) * 256, acc);
        int ocol0 = nh << 7;
        #pragma unroll
        for (int mi = 0; mi < 2; mi++) {
            int rl0 = w.warp_m*32 + mi*16 + (w.lane >> 2);
            int n0 = g_knn[bm + rl0], n1 = g_knn[bm + rl0 + 8];
            const __half* ckq0 = g_ckq16 + (size_t)(b*NP + n0)*256 + ocol0;
            const __half* ckq1 = g_ckq16 + (size_t)(b*NP + n1)*256 + ocol0;
            #pragma unroll
            for (int ni = 0; ni < 8; ni++) {
                int cl = w.warp_n*64 + ni*8 + ((w.lane & 3) << 1);
                __half2 k0 = *(const __half2*)(ckq0 + cl);
                __half2 k1 = *(const __half2*)(ckq1 + cl);
                float x0 = fmaxf(acc[mi][ni][0] + __low2float(k0), 0.f);
                float y0 = fmaxf(acc[mi][ni][1] + __high2float(k0), 0.f);
                float x1 = fmaxf(acc[mi][ni][2] + __low2float(k1), 0.f);
                float y1 = fmaxf(acc[mi][ni][3] + __high2float(k1), 0.f);
                int gcol = ocol0 + cl;
                int chunk = gcol >> 6, cin = gcol & 63;
                *(__half2*)(dynsm + 131072 + chunk*16384 + SW128((rl0 << 7) + (cin << 1))) =
                    __floats2half2_rn(x0, y0);
                *(__half2*)(dynsm + 131072 + chunk*16384 + SW128(((rl0+8) << 7) + (cin << 1))) =
                    __floats2half2_rn(x1, y1);
            }
        }
    }

    // ---- GEMM logits (2 halves, A = T) + softmax + output ----
    #pragma unroll
    for (int ny = 0; ny < 2; ny++) {
        half_gemm(w, tid, sT, sB, g_Wg2_16 + (size_t)(ny << 7) * 256, acc);
        __syncthreads();
        // stage logits (fp32 128x128) into A region, XOR-unitized
        #pragma unroll
        for (int mi = 0; mi < 2; mi++)
            #pragma unroll
            for (int ni = 0; ni < 8; ni++) {
                int rl = w.warp_m*32 + mi*16 + (w.lane >> 2);
                int cl = w.warp_n*64 + ni*8 + ((w.lane & 3) << 1);
                int u0 = ((cl >> 2) ^ (rl & 7));
                *(float2*)(dynsm + (rl << 9) + (u0 << 4) + ((cl & 3) << 2)) =
                    make_float2(acc[mi][ni][0], acc[mi][ni][1]);
                int u1 = ((cl >> 2) ^ ((rl+8) & 7));
                *(float2*)(dynsm + ((rl+8) << 9) + (u1 << 4) + ((cl & 3) << 2)) =
                    make_float2(acc[mi][ni][2], acc[mi][ni][3]);
            }
        __syncthreads();

        // warp = one query (16 rows), lane = 4 features of this 128-col half
        {
            const int qloc = w.wid;
            const int r0 = qloc << 4;
            const int gq = (bm >> 4) + qloc;
            const int f0 = w.lane << 2;
            const int gc = (ny << 7) + f0;
            const int pchunk = gc >> 6, pcin = gc & 63;

            float bgv0 = bg2[gc],   bgv1 = bg2[gc+1], bgv2 = bg2[gc+2], bgv3 = bg2[gc+3];
            float ag0 = g_ag[b*256+gc],   ag1 = g_ag[b*256+gc+1];
            float ag2 = g_ag[b*256+gc+2], ag3 = g_ag[b*256+gc+3];

            int nidx[16];
            #pragma unroll
            for (int j = 0; j < 16; j++) nidx[j] = g_knn[bm + r0 + j];

            float m0 = ag0, m1 = ag1, m2 = ag2, m3 = ag3;
            #pragma unroll
            for (int j = 0; j < 16; j++) {
                int r = r0 + j;
                float4 l = *(float4*)(dynsm + (r << 9) + ((((f0 >> 2)) ^ (r & 7)) << 4));
                m0 = fmaxf(m0, l.x + bgv0);
                m1 = fmaxf(m1, l.y + bgv1);
                m2 = fmaxf(m2, l.z + bgv2);
                m3 = fmaxf(m3, l.w + bgv3);
            }

            float s0 = __expf(ag0 - m0), s1 = __expf(ag1 - m1);
            float s2 = __expf(ag2 - m2), s3 = __expf(ag3 - m3);
            float o0 = s0 * g_vg[b*256+gc],   o1 = s1 * g_vg[b*256+gc+1];
            float o2 = s2 * g_vg[b*256+gc+2], o3 = s3 * g_vg[b*256+gc+3];

            #pragma unroll
            for (int j = 0; j < 16; j++) {
                int r = r0 + j;
                float4 l = *(float4*)(dynsm + (r << 9) + ((((f0 >> 2)) ^ (r & 7)) << 4));
                uint2 pu = *(uint2*)(dynsm + 65536 + pchunk*16384 + SW128((r << 7) + (pcin << 1)));
                uint2 vu = *(const uint2*)(g_v16 + ((size_t)(b*NP + nidx[j]))*256 + gc);
                __half2 p01 = *reinterpret_cast<__half2*>(&pu.x);
                __half2 p23 = *reinterpret_cast<__half2*>(&pu.y);
                __half2 v01 = *reinterpret_cast<__half2*>(&vu.x);
                __half2 v23 = *reinterpret_cast<__half2*>(&vu.y);
                float e0 = __expf(l.x + bgv0 - m0);
                float e1 = __expf(l.y + bgv1 - m1);
                float e2 = __expf(l.z + bgv2 - m2);
                float e3 = __expf(l.w + bgv3 - m3);
                s0 += e0; s1 += e1; s2 += e2; s3 += e3;
                o0 = fmaf(e0, __low2float(v01)  + __low2float(p01),  o0);
                o1 = fmaf(e1, __high2float(v01) + __high2float(p01), o1);
                o2 = fmaf(e2, __low2float(v23)  + __low2float(p23),  o2);
                o3 = fmaf(e3, __high2float(v23) + __high2float(p23), o3);
            }
            *(float4*)(out + (size_t)gq*256 + gc) = make_float4(o0/s0, o1/s1, o2/s2, o3/s3);
        }
        __syncthreads();
    }
}

// ================= launch =================
extern "C" void kernel_launch(void* const* d_in, const int* in_sizes, int n_in,
                              void* d_out, int out_size)
{
    const float* xyz_q  = (const float*)d_in[0];
    const float* lat    = (const float*)d_in[1];
    const float* xyz    = (const float*)d_in[2];
    const float* points = (const float*)d_in[3];
    const float* Wd1 = (const float*)d_in[4];  const float* bd1 = (const float*)d_in[5];
    const float* Wd2 = (const float*)d_in[6];  const float* bd2 = (const float*)d_in[7];
    const float* Wg1 = (const float*)d_in[8];  const float* bg1 = (const float*)d_in[9];
    const float* Wg2 = (const float*)d_in[10]; const float* bg2 = (const float*)d_in[11];
    const float* Wkg = (const float*)d_in[12]; const float* Wvg = (const float*)d_in[13];
    const float* Wq  = (const float*)d_in[14]; const float* Wk  = (const float*)d_in[15];
    const float* Wv  = (const float*)d_in[16];
    float* out = (float*)d_out;
    (void)in_sizes; (void)n_in; (void)out_size;

    const int FUSED_SMEM = 229376;   // A 64K + P 64K + T 64K + B 32K
    cudaFuncSetAttribute(hg_fused, cudaFuncAttributeMaxDynamicSharedMemorySize, FUSED_SMEM);
    const int KNN_SMEM = 32768;      // packed point cloud only
    cudaFuncSetAttribute(k_knn, cudaFuncAttributeMaxDynamicSharedMemorySize, KNN_SMEM);

    // 1
    k_prep<<<1025, 256>>>(Wd2, Wg1, Wk, Wg2, lat, Wq, Wkg, Wvg, bg1, bg2, bd2);
    // 2
    k_b3aq<<<(Bb*NP + Bb*NQ), 256>>>(xyz, xyz_q, Wd1, bd1);
    // 3
    sgemm<<<dim3(2, 64), 256>>>(points, nullptr, 0);   // ckq (fp16, pre-folded)
    // 4  <- profiled slot: verify the new KNN
    k_knn<<<Bb*NQ/32, 256, KNN_SMEM>>>(xyz, xyz_q);
    // 5
    sgemm<<<dim3(2, 64), 256>>>(points, Wv,      1);   // v (fp16)
    // 6  fused pair pipeline (pos + t + logits + softmax + output)
    hg_fused<<<PAIR_ROWS/128, 256, FUSED_SMEM>>>(bd2, bg2, out);
}

// round 16
// speedup vs baseline: 1.0452x; 1.0452x over previous
#include <cuda_runtime.h>
#include <cuda_fp16.h>
#include <math_constants.h>
#include <cstdint>

#define Bb   4
#define NQ   4096
#define NP   2048
#define D    256
#define KNN  16
#define PAIR_ROWS (Bb*NQ*KNN)   /* 262144 */

// ================= PTX helpers (baseline ISA — no tcgen05) =================
__device__ __forceinline__ uint32_t smem_to_u32(const void* p) {
    uint32_t a;
    asm("{ .reg .u64 t; cvta.to.shared.u64 t, %1; cvt.u32.u64 %0, t; }" : "=r"(a) : "l"(p));
    return a;
}
#define CP_ASYNC16(dst, src) \
    asm volatile("cp.async.cg.shared.global [%0], [%1], 16;" :: "r"(dst), "l"(src))
#define CP_COMMIT() asm volatile("cp.async.commit_group;" ::: "memory")
template<int N> __device__ __forceinline__ void cp_wait() {
    asm volatile("cp.async.wait_group %0;" :: "n"(N) : "memory");
}
#define LDSM_X4(r0,r1,r2,r3, addr) \
    asm volatile("ldmatrix.sync.aligned.m8n8.x4.shared.b16 {%0,%1,%2,%3}, [%4];" \
        : "=r"(r0), "=r"(r1), "=r"(r2), "=r"(r3) : "r"(addr))
#define MMA16816(cc, a0,a1,a2,a3, b0,b1) \
    asm volatile("mma.sync.aligned.m16n8k16.row.col.f32.f16.f16.f32 " \
        "{%0,%1,%2,%3}, {%4,%5,%6,%7}, {%8,%9}, {%0,%1,%2,%3};" \
        : "+f"((cc)[0]), "+f"((cc)[1]), "+f"((cc)[2]), "+f"((cc)[3]) \
        : "r"(a0), "r"(a1), "r"(a2), "r"(a3), "r"(b0), "r"(b1))
#define SW128(off) ((off) ^ (((off) >> 3) & 0x70))

// ================= scratch (device globals) =================
__device__ __align__(16) __half g_ckq16[Bb*NP*D]; // cq + c0 - (Wg1@Wk)points  (fp16, L2)
__device__ __align__(16) __half g_v16 [Bb*NP*D];  // points @ Wv^T (fp16, L2)
__device__ __align__(16) __half g_b316[Bb*NP*D];  // Wd1 @ xyz            (fp16)
__device__ __align__(16) __half g_aq16[Bb*NQ*D];  // Wd1 @ xyz_q + bd1    (fp16)
__device__ int    g_knn[Bb*NQ*KNN];
__device__ __align__(16) __half g_Wcat16[2*D*D];  // [Wd2 ; Md=Wg1@Wd2] fp16
__device__ __align__(16) __half g_Wg2_16[D*D];
__device__ float  g_Wkk [D*D];          // Wg1@Wk (fp32, for sgemm)
__device__ float  g_cq[Bb*D];           // Wg1 @ (Wq lat)
__device__ float  g_c0[D];              // Wg1@bd2 + bg1
__device__ float  g_ag[Bb*D];           // gamma-MLP output for global token
__device__ float  g_vg[Bb*D];           // Wvg lat

// ================= k_prep =================
__device__ __forceinline__ float dot256(const float* __restrict__ w, const float* __restrict__ s)
{
    float acc = 0.f;
    #pragma unroll 8
    for (int c = 0; c < 256; c++) acc = fmaf(w[c], s[c], acc);
    return acc;
}

__global__ void k_prep(const float* __restrict__ Wd2, const float* __restrict__ Wg1,
                       const float* __restrict__ Wk,  const float* __restrict__ Wg2,
                       const float* __restrict__ lat,
                       const float* __restrict__ Wq,  const float* __restrict__ Wkg,
                       const float* __restrict__ Wvg, const float* __restrict__ bg1,
                       const float* __restrict__ bg2, const float* __restrict__ bd2)
{
    int blk = blockIdx.x;
    int tid = threadIdx.x;
    if (blk < 1024) {
        int gid = blk * 256 + tid;
        if (gid < D*D) {
            g_Wcat16[gid] = __float2half(Wd2[gid]);
        } else if (gid < 2*D*D) {
            int i = gid - D*D; int f = i >> 8, j = i & 255;
            float acc = 0.f;
            #pragma unroll 8
            for (int c = 0; c < D; c++) acc = fmaf(Wg1[f*D+c], Wd2[c*D+j], acc);
            g_Wcat16[D*D + i] = __float2half(acc);
        } else if (gid < 3*D*D) {
            int i = gid - 2*D*D; int f = i >> 8, j = i & 255;
            float acc = 0.f;
            #pragma unroll 8
            for (int c = 0; c < D; c++) acc = fmaf(Wg1[f*D+c], Wk[c*D+j], acc);
            g_Wkk[i] = acc;
        } else {
            int i = gid - 3*D*D;
            g_Wg2_16[i] = __float2half(Wg2[i]);
        }
        return;
    }
    __shared__ float s_in[256], s_qa[256], s_x[256], s_t[256];
    int f = tid;
    {
        float acc = bg1[f];
        #pragma unroll 8
        for (int c = 0; c < 256; c++) acc = fmaf(Wg1[f*256+c], bd2[c], acc);
        g_c0[f] = acc;
    }
    for (int b = 0; b < Bb; b++) {
        __syncthreads();
        s_in[f] = lat[b*256+f];
        __syncthreads();
        float qa = dot256(Wq  + f*256, s_in);
        float kg = dot256(Wkg + f*256, s_in);
        g_vg[b*256+f] = dot256(Wvg + f*256, s_in);
        __syncthreads();
        s_qa[f] = qa;
        s_x [f] = qa - kg;
        __syncthreads();
        g_cq[b*256+f] = dot256(Wg1 + f*256, s_qa);
        float tg = dot256(Wg1 + f*256, s_x) + bg1[f];
        s_t[f] = fmaxf(tg, 0.f);
        __syncthreads();
        g_ag[b*256+f] = dot256(Wg2 + f*256, s_t) + bg2[f];
    }
}

// ================= 3->256 coordinate projections (fp16 out) =================
__global__ void k_b3aq(const float* __restrict__ xyz, const float* __restrict__ xyz_q,
                       const float* __restrict__ Wd1, const float* __restrict__ bd1)
{
    int gid = blockIdx.x * 256 + threadIdx.x;
    int row = gid >> 8, f = gid & 255;
    float w0 = Wd1[f*3+0], w1 = Wd1[f*3+1], w2 = Wd1[f*3+2];
    if (row < Bb*NP) {
        const float* p = xyz + row*3;
        g_b316[gid] = __float2half(fmaf(w0, p[0], fmaf(w1, p[1], w2 * p[2])));
    } else {
        int r = row - Bb*NP; if (r >= Bb*NQ) return;
        const float* p = xyz_q + r*3;
        g_aq16[r*256+f] = __float2half(fmaf(w0, p[0], fmaf(w1, p[1], fmaf(w2, p[2], bd1[f]))));
    }
}

// ================= KNN (R13 proven): 256 thr, 64 queries/block, float4 points =====
// dyn smem: [sp4: 2048 float4 = 32KB][cd: 64x64 fp32 = 16KB][ci: 64x64 u16 = 8KB]
__global__ __launch_bounds__(256) void k_knn(const float* __restrict__ xyz,
                                             const float* __restrict__ xyz_q)
{
    extern __shared__ __align__(16) char knnsm[];
    float4* sp4 = (float4*)knnsm;                       // 2048 entries
    float*  cd  = (float*)(knnsm + 32768);              // [entry e][query qi] e*64+qi
    unsigned short* ci = (unsigned short*)(knnsm + 49152);

    int tid = threadIdx.x;
    int qi = tid >> 2, sub = tid & 3;                   // 64 queries, 4 subs each
    int q  = blockIdx.x * 64 + qi;                      // b*4096 + q
    int b  = q >> 12;
    const float* xb = xyz + b * NP * 3;
    for (int i = tid; i < NP; i += 256) {
        float x = xb[i*3], y = xb[i*3+1], z = xb[i*3+2];
        sp4[i] = make_float4(x, y, z, x*x + y*y + z*z);
    }
    __syncthreads();
    const float* qp = xyz_q + q*3;
    float qx = qp[0], qy = qp[1], qz = qp[2];
    float qn2 = qx*qx + qy*qy + qz*qz;

    float dist[KNN]; int idxr[KNN];
    #pragma unroll
    for (int j = 0; j < KNN; j++) { dist[j] = CUDART_INF_F; idxr[j] = 0; }
    float worst = CUDART_INF_F; int ws = 0;
    for (int k = 0; k < 512; k++) {
        int n = (k << 2) | sub;                          // warp-broadcast LDS.128
        float4 p = sp4[n];
        float dp = fmaf(qx, p.x, fmaf(qy, p.y, qz * p.z));
        float d2 = qn2 + p.w - 2.f * dp;                 // identical formula to reference
        if (d2 < worst) {
            #pragma unroll
            for (int j = 0; j < KNN; j++) if (j == ws) { dist[j] = d2; idxr[j] = n; }
            worst = dist[0]; ws = 0;
            #pragma unroll
            for (int j = 1; j < KNN; j++) if (dist[j] > worst) { worst = dist[j]; ws = j; }
        }
    }
    #pragma unroll
    for (int j = 0; j < KNN; j++) {
        int e = sub * KNN + j;
        cd[e*64 + qi] = dist[j];
        ci[e*64 + qi] = (unsigned short)idxr[j];
    }
    __syncthreads();
    if (tid < 64) {
        int qg = blockIdx.x * 64 + tid;
        for (int s = 0; s < KNN; s++) {
            float best = CUDART_INF_F; int be = 0;
            #pragma unroll 8
            for (int e = 0; e < 64; e++) {
                float v = cd[e*64 + tid];
                if (v < best) { best = v; be = e; }
            }
            g_knn[qg*KNN + s] = (int)ci[be*64 + tid];
            cd[be*64 + tid] = CUDART_INF_F;
        }
    }
}

// ================= SIMT fp32 GEMM for per-point ckq / v (combined launch) =========
// blockIdx.z == 0: g_ckq16 = fp16(cq + c0 - points @ Wkk^T)
// blockIdx.z == 1: g_v16   = fp16(points @ Wv^T)
__global__ __launch_bounds__(256) void sgemm(const float* __restrict__ A,
                                             const float* __restrict__ Wv)
{
    __shared__ float As[16][132];
    __shared__ float Ws[16][132];
    const int mode = blockIdx.z;
    const float* W = (mode == 0) ? g_Wkk : Wv;
    const int bm = blockIdx.y << 7;
    const int bn = blockIdx.x << 7;
    const int tid = threadIdx.x;
    const int tx = tid & 15, ty = tid >> 4;

    float acc[8][8];
    #pragma unroll
    for (int i = 0; i < 8; i++)
        #pragma unroll
        for (int j = 0; j < 8; j++) acc[i][j] = 0.f;

    for (int k0 = 0; k0 < 256; k0 += 16) {
        #pragma unroll
        for (int i = 0; i < 2; i++) {
            int l = tid + (i << 8);
            int r = l >> 2, kc = (l & 3) << 2;
            float4 va = *(const float4*)(A + (bm + r) * 256 + k0 + kc);
            As[kc+0][r] = va.x; As[kc+1][r] = va.y; As[kc+2][r] = va.z; As[kc+3][r] = va.w;
            float4 vw = *(const float4*)(W + (bn + r) * 256 + k0 + kc);
            Ws[kc+0][r] = vw.x; Ws[kc+1][r] = vw.y; Ws[kc+2][r] = vw.z; Ws[kc+3][r] = vw.w;
        }
        __syncthreads();
        #pragma unroll
        for (int kk = 0; kk < 16; kk++) {
            float a[8], bb[8];
            *(float4*)(a)      = *(const float4*)&As[kk][ty << 3];
            *(float4*)(a + 4)  = *(const float4*)&As[kk][(ty << 3) + 4];
            *(float4*)(bb)     = *(const float4*)&Ws[kk][tx << 3];
            *(float4*)(bb + 4) = *(const float4*)&Ws[kk][(tx << 3) + 4];
            #pragma unroll
            for (int i = 0; i < 8; i++)
                #pragma unroll
                for (int j = 0; j < 8; j++) acc[i][j] = fmaf(a[i], bb[j], acc[i][j]);
        }
        __syncthreads();
    }
    int cc = bn + (tx << 3);
    if (mode == 0) {
        #pragma unroll
        for (int i = 0; i < 8; i++) {
            int m = bm + (ty << 3) + i;
            int b = m >> 11;
            __half hh[8];
            #pragma unroll
            for (int j = 0; j < 8; j++)
                hh[j] = __float2half(g_cq[b*256 + cc + j] + g_c0[cc + j] - acc[i][j]);
            *(uint4*)(g_ckq16 + (size_t)m*256 + cc) = *(uint4*)hh;
        }
    } else {
        #pragma unroll
        for (int i = 0; i < 8; i++) {
            int m = bm + (ty << 3) + i;
            __half hh[8];
            #pragma unroll
            for (int j = 0; j < 8; j++) hh[j] = __float2half(acc[i][j]);
            *(uint4*)(g_v16 + (size_t)m*256 + cc) = *(uint4*)hh;
        }
    }
}

// ===================================================================
// Fused pair pipeline. CTA = 128 pair rows (8 queries), 256 threads.
// SMEM: [A/h 64K][P/pos 64K][T/t 64K][B 2x16K] = 224KB, 1 CTA/SM.
// ===================================================================
struct WarpCtx {
    int lane, wid, warp_m, warp_n;
    int a_row, a_seg, b_row_base, b_seg;
};
__device__ __forceinline__ WarpCtx make_ctx(int tid) {
    WarpCtx w;
    w.lane = tid & 31; w.wid = tid >> 5;
    w.warp_m = w.wid >> 1; w.warp_n = w.wid & 1;
    int lr = w.lane & 7, sel = w.lane >> 3;
    w.a_row = w.warp_m*32 + lr + (sel & 1)*8;
    w.a_seg = sel >> 1;
    w.b_row_base = w.warp_n*64 + lr + (sel >> 1)*8;
    w.b_seg = sel & 1;
    return w;
}

__device__ __forceinline__ void mma_chunk(const WarpCtx& w, uint32_t bufA, uint32_t bufB,
                                          float acc[2][8][4])
{
    #pragma unroll
    for (int ks = 0; ks < 4; ks++) {
        uint32_t a[2][4], bf[4][4];
        #pragma unroll
        for (int mi = 0; mi < 2; mi++) {
            uint32_t ad = bufA + SW128(((w.a_row + mi*16) << 7) + ((w.a_seg + ks*2) << 4));
            LDSM_X4(a[mi][0], a[mi][1], a[mi][2], a[mi][3], ad);
        }
        #pragma unroll
        for (int nj = 0; nj < 4; nj++) {
            uint32_t bd = bufB + SW128(((w.b_row_base + nj*16) << 7) + ((w.b_seg + ks*2) << 4));
            LDSM_X4(bf[nj][0], bf[nj][1], bf[nj][2], bf[nj][3], bd);
        }
        #pragma unroll
        for (int mi = 0; mi < 2; mi++)
            #pragma unroll
            for (int ni = 0; ni < 8; ni++)
                MMA16816(acc[mi][ni], a[mi][0], a[mi][1], a[mi][2], a[mi][3],
                         bf[ni>>1][(ni&1)*2], bf[ni>>1][(ni&1)*2 + 1]);
    }
}

// One 128x128 half-GEMM: A (K=256, swizzled, 4x16KB at Abase), B streamed from Bop.
__device__ __forceinline__ void half_gemm(const WarpCtx& w, int tid,
                                          uint32_t Abase, uint32_t sB,
                                          const __half* __restrict__ Bop,
                                          float acc[2][8][4])
{
    const int lseg = tid & 7;
    #pragma unroll
    for (int mi = 0; mi < 2; mi++)
        #pragma unroll
        for (int ni = 0; ni < 8; ni++)
            #pragma unroll
            for (int k = 0; k < 4; k++) acc[mi][ni][k] = 0.f;
    #pragma unroll
    for (int c = 0; c < 2; c++) {
        #pragma unroll
        for (int i = 0; i < 4; i++) {
            int r = (tid >> 3) + (i << 5);
            CP_ASYNC16(sB + c*16384 + SW128((r << 7) + (lseg << 4)),
                       Bop + (size_t)r*256 + (c << 6) + (lseg << 3));
        }
        CP_COMMIT();
    }
    #pragma unroll
    for (int kc = 0; kc < 4; kc++) {
        if (kc < 3) cp_wait<1>(); else cp_wait<0>();
        __syncthreads();
        mma_chunk(w, Abase + kc*16384, sB + (kc & 1)*16384, acc);
        __syncthreads();
        if (kc < 2) {
            int c = kc + 2;
            #pragma unroll
            for (int i = 0; i < 4; i++) {
                int r = (tid >> 3) + (i << 5);
                CP_ASYNC16(sB + (c & 1)*16384 + SW128((r << 7) + (lseg << 4)),
                           Bop + (size_t)r*256 + (c << 6) + (lseg << 3));
            }
            CP_COMMIT();
        }
    }
}

__global__ __launch_bounds__(256, 1) void hg_fused(const float* __restrict__ bd2,
                                                   const float* __restrict__ bg2,
                                                   float* __restrict__ out)
{
    extern __shared__ __align__(16) char dynsm[];
    __shared__ float sBias[256];

    const int tid = threadIdx.x;
    const int bm  = blockIdx.x << 7;
    const int b   = bm >> 16;
    const uint32_t su = smem_to_u32(dynsm);
    const uint32_t sT = su + 131072;
    const uint32_t sB = su + 196608;
    WarpCtx w = make_ctx(tid);

    sBias[tid] = bd2[tid];

    // ---- regen h = relu(aq - b3[knn]) into A region (swizzled, 4x16KB chunks) ----
    const __half2 z2 = __floats2half2_rn(0.f, 0.f);
    #pragma unroll
    for (int c = 0; c < 4; c++) {
        #pragma unroll
        for (int i = 0; i < 4; i++) {
            int idx = tid + (i << 8);
            int r = idx >> 3, sg = idx & 7;
            int m = bm + r;
            int n = g_knn[m];
            uint4 ua = ((const uint4*)(g_aq16 + (size_t)(m >> 4)*256))[(c << 3) + sg];
            uint4 ub = ((const uint4*)(g_b316 + (size_t)(b*NP + n)*256))[(c << 3) + sg];
            __half2 a0 = *reinterpret_cast<__half2*>(&ua.x), p0 = *reinterpret_cast<__half2*>(&ub.x);
            __half2 a1 = *reinterpret_cast<__half2*>(&ua.y), p1 = *reinterpret_cast<__half2*>(&ub.y);
            __half2 a2 = *reinterpret_cast<__half2*>(&ua.z), p2 = *reinterpret_cast<__half2*>(&ub.z);
            __half2 a3 = *reinterpret_cast<__half2*>(&ua.w), p3 = *reinterpret_cast<__half2*>(&ub.w);
            __half2 h0 = __hmax2(__hsub2(a0, p0), z2);
            __half2 h1 = __hmax2(__hsub2(a1, p1), z2);
            __half2 h2 = __hmax2(__hsub2(a2, p2), z2);
            __half2 h3 = __hmax2(__hsub2(a3, p3), z2);
            uint4 u;
            u.x = reinterpret_cast<uint32_t&>(h0);
            u.y = reinterpret_cast<uint32_t&>(h1);
            u.z = reinterpret_cast<uint32_t&>(h2);
            u.w = reinterpret_cast<uint32_t&>(h3);
            *(uint4*)(dynsm + c*16384 + SW128((r << 7) + (sg << 4))) = u;
        }
    }

    float acc[2][8][4];

    // ---- GEMM pos (2 halves): P[:, nh*128+cl] = acc + bd2 ----
    #pragma unroll
    for (int nh = 0; nh < 2; nh++) {
        half_gemm(w, tid, su, sB, g_Wcat16 + (size_t)(nh << 7) * 256, acc);
        #pragma unroll
        for (int mi = 0; mi < 2; mi++)
            #pragma unroll
            for (int ni = 0; ni < 8; ni++) {
                int rl = w.warp_m*32 + mi*16 + (w.lane >> 2);
                int cl = w.warp_n*64 + ni*8 + ((w.lane & 3) << 1);
                int gcol = (nh << 7) + cl;
                int chunk = gcol >> 6, cin = gcol & 63;
                float bx = sBias[gcol], by = sBias[gcol+1];
                *(__half2*)(dynsm + 65536 + chunk*16384 + SW128((rl << 7) + (cin << 1))) =
                    __floats2half2_rn(acc[mi][ni][0] + bx, acc[mi][ni][1] + by);
                *(__half2*)(dynsm + 65536 + chunk*16384 + SW128(((rl+8) << 7) + (cin << 1))) =
                    __floats2half2_rn(acc[mi][ni][2] + bx, acc[mi][ni][3] + by);
            }
    }

    // ---- GEMM t (2 halves): T = relu(acc + ckq[knn]) ----
    #pragma unroll
    for (int nh = 0; nh < 2; nh++) {
        half_gemm(w, tid, su, sB, g_Wcat16 + (size_t)(256 + (nh << 7)) * 256, acc);
        int ocol0 = nh << 7;
        #pragma unroll
        for (int mi = 0; mi < 2; mi++) {
            int rl0 = w.warp_m*32 + mi*16 + (w.lane >> 2);
            int n0 = g_knn[bm + rl0], n1 = g_knn[bm + rl0 + 8];
            const __half* ckq0 = g_ckq16 + (size_t)(b*NP + n0)*256 + ocol0;
            const __half* ckq1 = g_ckq16 + (size_t)(b*NP + n1)*256 + ocol0;
            #pragma unroll
            for (int ni = 0; ni < 8; ni++) {
                int cl = w.warp_n*64 + ni*8 + ((w.lane & 3) << 1);
                __half2 k0 = *(const __half2*)(ckq0 + cl);
                __half2 k1 = *(const __half2*)(ckq1 + cl);
                float x0 = fmaxf(acc[mi][ni][0] + __low2float(k0), 0.f);
                float y0 = fmaxf(acc[mi][ni][1] + __high2float(k0), 0.f);
                float x1 = fmaxf(acc[mi][ni][2] + __low2float(k1), 0.f);
                float y1 = fmaxf(acc[mi][ni][3] + __high2float(k1), 0.f);
                int gcol = ocol0 + cl;
                int chunk = gcol >> 6, cin = gcol & 63;
                *(__half2*)(dynsm + 131072 + chunk*16384 + SW128((rl0 << 7) + (cin << 1))) =
                    __floats2half2_rn(x0, y0);
                *(__half2*)(dynsm + 131072 + chunk*16384 + SW128(((rl0+8) << 7) + (cin << 1))) =
                    __floats2half2_rn(x1, y1);
            }
        }
    }

    // ---- GEMM logits (2 halves, A = T) + softmax + output ----
    #pragma unroll
    for (int ny = 0; ny < 2; ny++) {
        half_gemm(w, tid, sT, sB, g_Wg2_16 + (size_t)(ny << 7) * 256, acc);
        __syncthreads();
        // stage logits (fp32 128x128) into A region, XOR-unitized
        #pragma unroll
        for (int mi = 0; mi < 2; mi++)
            #pragma unroll
            for (int ni = 0; ni < 8; ni++) {
                int rl = w.warp_m*32 + mi*16 + (w.lane >> 2);
                int cl = w.warp_n*64 + ni*8 + ((w.lane & 3) << 1);
                int u0 = ((cl >> 2) ^ (rl & 7));
                *(float2*)(dynsm + (rl << 9) + (u0 << 4) + ((cl & 3) << 2)) =
                    make_float2(acc[mi][ni][0], acc[mi][ni][1]);
                int u1 = ((cl >> 2) ^ ((rl+8) & 7));
                *(float2*)(dynsm + ((rl+8) << 9) + (u1 << 4) + ((cl & 3) << 2)) =
                    make_float2(acc[mi][ni][2], acc[mi][ni][3]);
            }
        __syncthreads();

        // warp = one query (16 rows), lane = 4 features of this 128-col half
        {
            const int qloc = w.wid;
            const int r0 = qloc << 4;
            const int gq = (bm >> 4) + qloc;
            const int f0 = w.lane << 2;
            const int gc = (ny << 7) + f0;
            const int pchunk = gc >> 6, pcin = gc & 63;

            float bgv0 = bg2[gc],   bgv1 = bg2[gc+1], bgv2 = bg2[gc+2], bgv3 = bg2[gc+3];
            float ag0 = g_ag[b*256+gc],   ag1 = g_ag[b*256+gc+1];
            float ag2 = g_ag[b*256+gc+2], ag3 = g_ag[b*256+gc+3];

            int nidx[16];
            #pragma unroll
            for (int j = 0; j < 16; j++) nidx[j] = g_knn[bm + r0 + j];

            float m0 = ag0, m1 = ag1, m2 = ag2, m3 = ag3;
            #pragma unroll
            for (int j = 0; j < 16; j++) {
                int r = r0 + j;
                float4 l = *(float4*)(dynsm + (r << 9) + ((((f0 >> 2)) ^ (r & 7)) << 4));
                m0 = fmaxf(m0, l.x + bgv0);
                m1 = fmaxf(m1, l.y + bgv1);
                m2 = fmaxf(m2, l.z + bgv2);
                m3 = fmaxf(m3, l.w + bgv3);
            }

            float s0 = __expf(ag0 - m0), s1 = __expf(ag1 - m1);
            float s2 = __expf(ag2 - m2), s3 = __expf(ag3 - m3);
            float o0 = s0 * g_vg[b*256+gc],   o1 = s1 * g_vg[b*256+gc+1];
            float o2 = s2 * g_vg[b*256+gc+2], o3 = s3 * g_vg[b*256+gc+3];

            #pragma unroll
            for (int j = 0; j < 16; j++) {
                int r = r0 + j;
                float4 l = *(float4*)(dynsm + (r << 9) + ((((f0 >> 2)) ^ (r & 7)) << 4));
                uint2 pu = *(uint2*)(dynsm + 65536 + pchunk*16384 + SW128((r << 7) + (pcin << 1)));
                uint2 vu = *(const uint2*)(g_v16 + ((size_t)(b*NP + nidx[j]))*256 + gc);
                __half2 p01 = *reinterpret_cast<__half2*>(&pu.x);
                __half2 p23 = *reinterpret_cast<__half2*>(&pu.y);
                __half2 v01 = *reinterpret_cast<__half2*>(&vu.x);
                __half2 v23 = *reinterpret_cast<__half2*>(&vu.y);
                float e0 = __expf(l.x + bgv0 - m0);
                float e1 = __expf(l.y + bgv1 - m1);
                float e2 = __expf(l.z + bgv2 - m2);
                float e3 = __expf(l.w + bgv3 - m3);
                s0 += e0; s1 += e1; s2 += e2; s3 += e3;
                o0 = fmaf(e0, __low2float(v01)  + __low2float(p01),  o0);
                o1 = fmaf(e1, __high2float(v01) + __high2float(p01), o1);
                o2 = fmaf(e2, __low2float(v23)  + __low2float(p23),  o2);
                o3 = fmaf(e3, __high2float(v23) + __high2float(p23), o3);
            }
            *(float4*)(out + (size_t)gq*256 + gc) = make_float4(o0/s0, o1/s1, o2/s2, o3/s3);
        }
        __syncthreads();
    }
}

// ================= launch =================
extern "C" void kernel_launch(void* const* d_in, const int* in_sizes, int n_in,
                              void* d_out, int out_size)
{
    const float* xyz_q  = (const float*)d_in[0];
    const float* lat    = (const float*)d_in[1];
    const float* xyz    = (const float*)d_in[2];
    const float* points = (const float*)d_in[3];
    const float* Wd1 = (const float*)d_in[4];  const float* bd1 = (const float*)d_in[5];
    const float* Wd2 = (const float*)d_in[6];  const float* bd2 = (const float*)d_in[7];
    const float* Wg1 = (const float*)d_in[8];  const float* bg1 = (const float*)d_in[9];
    const float* Wg2 = (const float*)d_in[10]; const float* bg2 = (const float*)d_in[11];
    const float* Wkg = (const float*)d_in[12]; const float* Wvg = (const float*)d_in[13];
    const float* Wq  = (const float*)d_in[14]; const float* Wk  = (const float*)d_in[15];
    const float* Wv  = (const float*)d_in[16];
    float* out = (float*)d_out;
    (void)in_sizes; (void)n_in; (void)out_size;

    const int FUSED_SMEM = 229376;   // A 64K + P 64K + T 64K + B 32K
    cudaFuncSetAttribute(hg_fused, cudaFuncAttributeMaxDynamicSharedMemorySize, FUSED_SMEM);
    const int KNN_SMEM = 57344;      // 32K pts + 16K cd + 8K ci
    cudaFuncSetAttribute(k_knn, cudaFuncAttributeMaxDynamicSharedMemorySize, KNN_SMEM);

    // 1
    k_prep<<<1025, 256>>>(Wd2, Wg1, Wk, Wg2, lat, Wq, Wkg, Wvg, bg1, bg2, bd2);
    // 2
    k_b3aq<<<(Bb*NP + Bb*NQ), 256>>>(xyz, xyz_q, Wd1, bd1);
    // 3  combined per-point projections (ckq + v in one launch)
    sgemm<<<dim3(2, 64, 2), 256>>>(points, Wv);
    // 4  <- profiled slot: KNN (expect ~246us, R13 config)
    k_knn<<<Bb*NQ/64, 256, KNN_SMEM>>>(xyz, xyz_q);
    // 5  fused pair pipeline (pos + t + logits + softmax + output)
    hg_fused<<<PAIR_ROWS/128, 256, FUSED_SMEM>>>(bd2, bg2, out);
}